// round 4
// baseline (speedup 1.0000x reference)
#include <cuda_runtime.h>
#include <math.h>

// ---------------------------------------------------------------------------
// unit_gcn fused kernel, fp32 with packed f32x2 FMA.  W-first ordering:
//   P_s = (BN-folded Wd_s) @ X   (64x64 @ 64x200 per 8-frame tile)
//   Y  += sum_v P_s[o][t,v] * Af_s[v][w]
// 640 threads/block (5 warps/SMSP) for latency hiding.
// Shapes: N=128, C=Cout=64, T=256, V=25, S=3, RED=4, KER=25, PAD=12.
// ---------------------------------------------------------------------------

typedef unsigned long long ull;

__device__ __forceinline__ ull pk2(float lo, float hi) {
    ull r;
    asm("mov.b64 %0, {%1, %2};" : "=l"(r) : "f"(lo), "f"(hi));
    return r;
}
__device__ __forceinline__ void fma2(ull &d, ull a, ull b) {
    asm("fma.rn.f32x2 %0, %1, %2, %0;" : "+l"(d) : "l"(a), "l"(b));
}
__device__ __forceinline__ float2 up2(ull v) {
    float2 r;
    asm("mov.b64 {%0, %1}, %2;" : "=f"(r.x), "=f"(r.y) : "l"(v));
    return r;
}

// ------------------------- device scratch (no allocs) ----------------------
__device__ float d_Afp[3 * 25 * 26];          // Af padded to stride 26 (1950 floats)
__device__ float d_Wc[192 * 64];              // d_Wc[(s*64+c)*64 + o] = wd[s,o,c]*bn_scale[o]
__device__ float d_Kc[64];                    // per-channel additive const
__device__ float d_pp[32 * 128 * 1600];       // per-(ttile,n) partial T-sums of y
__device__ float d_g[128 * 64 * 25];          // final multiplier (1 + sigmoid)

// ------------------------------- prep --------------------------------------
__global__ void prep_kernel(const float* __restrict__ A, const float* __restrict__ PA,
                            const float* __restrict__ wd, const float* __restrict__ bd,
                            const float* __restrict__ gamma, const float* __restrict__ beta,
                            const float* __restrict__ mean, const float* __restrict__ var)
{
    int tid = threadIdx.x;
    __shared__ float ssc[64];
    if (tid < 64) {
        float sc = gamma[tid] * rsqrtf(var[tid] + 1e-5f);
        ssc[tid] = sc;
        d_Kc[tid] = (bd[tid] + bd[64 + tid] + bd[128 + tid]) * sc
                    + beta[tid] - mean[tid] * sc;
    }
    __syncthreads();
    for (int idx = tid; idx < 75; idx += blockDim.x) {
        int s = idx / 25, w = idx % 25;
        float nrm = 0.f;
        for (int v = 0; v < 25; v++) {
            float pv = PA[(s * 25 + v) * 25 + w];
            nrm += pv * pv;
        }
        nrm = sqrtf(nrm) + 1e-4f;
        for (int v = 0; v < 25; v++)
            d_Afp[(s * 25 + v) * 26 + w] =
                A[(s * 25 + v) * 25 + w] + PA[(s * 25 + v) * 25 + w] / nrm;
        d_Afp[idx * 26 + 25] = 0.f;
    }
    for (int idx = tid; idx < 12288; idx += blockDim.x) {
        int k = idx >> 6, o = idx & 63;
        int s = k >> 6, c = k & 63;
        d_Wc[idx] = wd[(s * 64 + o) * 64 + c] * ssc[o];
    }
}

// ------------------------------- main ---------------------------------------
// One block per (n, 8-frame tile).  640 threads.
// smem: xs[64*200] | Ps[64*200] | Wcs[192*64] | Afd[75*26 ull] | Kcs[64]
#define AFD_FLOATS (3 * 25 * 26 * 2)   /* 3900 */
#define SMEM_FLOATS (64*200 + 64*200 + 192*64 + AFD_FLOATS + 64)

__global__ void __launch_bounds__(640, 1)
main_kernel(const float* __restrict__ x, float* __restrict__ out)
{
    extern __shared__ float sm[];
    float* xs  = sm;                   // 12800 floats
    float* Ps  = sm + 12800;           // 12800 floats
    float* Wcs = Ps + 12800;           // 12288 floats
    float* Afdf= Wcs + 12288;          // 3900 floats (ull-aligned: offset 37888*4 B)
    float* Kcs = Afdf + AFD_FLOATS;    // 64 floats
    ull*   Afd = (ull*)Afdf;
    float* ps  = Ps;                   // reuse for per-block T-sum (1600)

    const int tid = threadIdx.x;
    const int n   = blockIdx.y;
    const int t0  = blockIdx.x * 8;

    // cooperative loads
    {
        const float* xb = x + (size_t)n * 64 * 6400 + t0 * 25;
        for (int idx = tid; idx < 64 * 200; idx += 640) {
            int c = idx / 200, r = idx - c * 200;
            xs[c * 200 + r] = xb[c * 6400 + r];
        }
        for (int idx = tid; idx < 12288; idx += 640) Wcs[idx] = d_Wc[idx];
        for (int idx = tid; idx < 1950; idx += 640) {
            float f = d_Afp[idx];
            Afd[idx] = pk2(f, f);
        }
        if (tid < 64) Kcs[tid] = d_Kc[tid];
    }
    __syncthreads();

    const int m     = tid / 40;          // o-block (4 rows: o = 4m..4m+3), 0..15
    const int nn    = tid - m * 40;      // tw-block (5 cols)
    const int t_idx = nn / 5;            // frame within tile (0..7)
    const int w0    = (nn - t_idx * 5) * 5;
    const int col0  = t_idx * 25 + w0;   // output column base (tw)

    ull yacc[2][5];
    #pragma unroll
    for (int p = 0; p < 2; p++)
        #pragma unroll
        for (int j = 0; j < 5; j++) yacc[p][j] = 0ull;

    for (int s = 0; s < 3; s++) {
        // ---- stage 1: P = Wd_s @ X  (per-thread 4o x 5tv f32x2 tile) ----
        ull pacc[2][5];
        #pragma unroll
        for (int p = 0; p < 2; p++)
            #pragma unroll
            for (int j = 0; j < 5; j++) pacc[p][j] = 0ull;

        const float* wptr = &Wcs[(s << 12) + 4 * m];   // +64 per c
        const float* xptr = &xs[nn * 5];               // +200 per c
        #pragma unroll 4
        for (int c = 0; c < 64; c++) {
            ulonglong2 W = *(const ulonglong2*)(wptr);  // {o0,o1},{o2,o3}
            ull b0 = pk2(xptr[0], xptr[0]);
            ull b1 = pk2(xptr[1], xptr[1]);
            ull b2 = pk2(xptr[2], xptr[2]);
            ull b3 = pk2(xptr[3], xptr[3]);
            ull b4 = pk2(xptr[4], xptr[4]);
            fma2(pacc[0][0], W.x, b0); fma2(pacc[0][1], W.x, b1);
            fma2(pacc[0][2], W.x, b2); fma2(pacc[0][3], W.x, b3);
            fma2(pacc[0][4], W.x, b4);
            fma2(pacc[1][0], W.y, b0); fma2(pacc[1][1], W.y, b1);
            fma2(pacc[1][2], W.y, b2); fma2(pacc[1][3], W.y, b3);
            fma2(pacc[1][4], W.y, b4);
            wptr += 64;
            xptr += 200;
        }

        __syncthreads();   // previous stage-2 readers of Ps are done
        #pragma unroll
        for (int p = 0; p < 2; p++) {
            int o0 = 4 * m + 2 * p;
            #pragma unroll
            for (int j = 0; j < 5; j++) {
                float2 t2 = up2(pacc[p][j]);
                Ps[o0 * 200 + col0 + j]       = t2.x;
                Ps[(o0 + 1) * 200 + col0 + j] = t2.y;
            }
        }
        __syncthreads();   // Ps ready

        // ---- stage 2: yacc += sum_v P[o][t,v] * Af_s[v][w] ----
        const ull* afb = &Afd[s * 25 * 26 + w0];
        const float* pb0 = &Ps[(4 * m) * 200 + t_idx * 25];
        #pragma unroll 5
        for (int v = 0; v < 25; v++) {
            const ull* afr = afb + v * 26;
            ull a0 = afr[0];
            ull a1 = afr[1];
            ull a2 = afr[2];
            ull a3 = afr[3];
            ull a4 = afr[4];
            ull pv0 = pk2(pb0[v],        pb0[200 + v]);
            ull pv1 = pk2(pb0[400 + v],  pb0[600 + v]);
            fma2(yacc[0][0], pv0, a0);
            fma2(yacc[0][1], pv0, a1);
            fma2(yacc[0][2], pv0, a2);
            fma2(yacc[0][3], pv0, a3);
            fma2(yacc[0][4], pv0, a4);
            fma2(yacc[1][0], pv1, a0);
            fma2(yacc[1][1], pv1, a1);
            fma2(yacc[1][2], pv1, a2);
            fma2(yacc[1][3], pv1, a3);
            fma2(yacc[1][4], pv1, a4);
        }
    }

    __syncthreads();
    for (int idx = tid; idx < 1600; idx += 640) ps[idx] = 0.f;

    // ---- epilogue: BN-const + residual + ReLU
    float yv[2][5][2];
    #pragma unroll
    for (int p = 0; p < 2; p++) {
        int o0 = 4 * m + 2 * p;
        float kc0 = Kcs[o0], kc1 = Kcs[o0 + 1];
        #pragma unroll
        for (int j = 0; j < 5; j++) {
            float2 t2 = up2(yacc[p][j]);
            float r0 = t2.x + kc0 + xs[o0 * 200 + col0 + j];
            float r1 = t2.y + kc1 + xs[(o0 + 1) * 200 + col0 + j];
            yv[p][j][0] = fmaxf(r0, 0.f);
            yv[p][j][1] = fmaxf(r1, 0.f);
        }
    }
    // global stores of y (into d_out; final pass multiplies in place)
    {
        float* ob = out + (size_t)n * 64 * 6400 + (t0 + t_idx) * 25 + w0;
        #pragma unroll
        for (int p = 0; p < 2; p++) {
            int o0 = 4 * m + 2 * p;
            #pragma unroll
            for (int j = 0; j < 5; j++) {
                ob[o0 * 6400 + j]       = yv[p][j][0];
                ob[(o0 + 1) * 6400 + j] = yv[p][j][1];
            }
        }
    }
    // deterministic within-block T-reduction (phase-ordered, no atomics)
    __syncthreads();
    for (int tp = 0; tp < 8; tp++) {
        if (t_idx == tp) {
            #pragma unroll
            for (int p = 0; p < 2; p++) {
                int o0 = 4 * m + 2 * p;
                #pragma unroll
                for (int j = 0; j < 5; j++) {
                    ps[o0 * 25 + w0 + j]       += yv[p][j][0];
                    ps[(o0 + 1) * 25 + w0 + j] += yv[p][j][1];
                }
            }
        }
        __syncthreads();
    }
    float* pout = &d_pp[((size_t)blockIdx.x * 128 + n) * 1600];
    for (int idx = tid; idx < 1600; idx += 640) pout[idx] = ps[idx];
}

// ------------------------------- gate ---------------------------------------
__global__ void gate_kernel(const float* __restrict__ ws, const float* __restrict__ bs,
                            const float* __restrict__ we, const float* __restrict__ be)
{
    __shared__ float p[1600];
    __shared__ float sbuf[100];
    const int n = blockIdx.x, tid = threadIdx.x;   // 128 threads
    for (int idx = tid; idx < 1600; idx += 128) {
        float acc = 0.f;
        for (int tile = 0; tile < 32; tile++)
            acc += d_pp[((size_t)tile * 128 + n) * 1600 + idx];
        p[idx] = acc * (1.0f / 256.0f);
    }
    __syncthreads();
    if (tid < 100) {
        int r = tid / 25, v = tid % 25;
        float acc = bs[r];
        int k0 = 12 - v; if (k0 < 0) k0 = 0;
        int k1 = 36 - v; if (k1 > 24) k1 = 24;
        for (int c = 0; c < 64; c++) {
            const float* wr = &ws[(r * 64 + c) * 25];
            const float* pc = &p[c * 25 + v - 12];
            for (int k = k0; k <= k1; k++)
                acc = fmaf(pc[k], wr[k], acc);
        }
        sbuf[tid] = fmaxf(acc, 0.f);
    }
    __syncthreads();
    for (int idx = tid; idx < 1600; idx += 128) {
        int o = idx / 25, v = idx % 25;
        float z = be[o];
        #pragma unroll
        for (int r = 0; r < 4; r++)
            z = fmaf(sbuf[r * 25 + v], we[o * 4 + r], z);
        d_g[n * 1600 + idx] = 1.f + 1.f / (1.f + expf(-z));
    }
}

// ------------------------------- final --------------------------------------
__global__ void final_kernel(float* __restrict__ out)
{
    unsigned i = blockIdx.x * blockDim.x + threadIdx.x;   // float4 index
    float4 v = reinterpret_cast<float4*>(out)[i];
    unsigned flat = i * 4u;
    unsigned q  = flat / 25u;
    unsigned v0 = flat - q * 25u;
    unsigned co = q / 256u;                                // (n*64+o); constant in a float4
    const float* gr = d_g + (size_t)co * 25u;
    unsigned v1 = v0 + 1u; if (v1 >= 25u) v1 -= 25u;
    unsigned v2 = v0 + 2u; if (v2 >= 25u) v2 -= 25u;
    unsigned v3 = v0 + 3u; if (v3 >= 25u) v3 -= 25u;
    v.x *= gr[v0]; v.y *= gr[v1]; v.z *= gr[v2]; v.w *= gr[v3];
    reinterpret_cast<float4*>(out)[i] = v;
}

// ------------------------------ launcher -------------------------------------
extern "C" void kernel_launch(void* const* d_in, const int* in_sizes, int n_in,
                              void* d_out, int out_size)
{
    const float* x     = (const float*)d_in[0];
    const float* A     = (const float*)d_in[1];
    const float* PA    = (const float*)d_in[2];
    const float* wd    = (const float*)d_in[3];
    const float* bd    = (const float*)d_in[4];
    const float* gamma = (const float*)d_in[5];
    const float* beta  = (const float*)d_in[6];
    const float* mean  = (const float*)d_in[7];
    const float* var   = (const float*)d_in[8];
    const float* sws   = (const float*)d_in[9];
    const float* sbs   = (const float*)d_in[10];
    const float* swe   = (const float*)d_in[11];
    const float* sbe   = (const float*)d_in[12];
    float* out = (float*)d_out;

    const int smem_bytes = SMEM_FLOATS * (int)sizeof(float);  // 167408
    cudaFuncSetAttribute(main_kernel, cudaFuncAttributeMaxDynamicSharedMemorySize,
                         smem_bytes);

    prep_kernel<<<1, 256>>>(A, PA, wd, bd, gamma, beta, mean, var);
    dim3 grid(32, 128);
    main_kernel<<<grid, 640, smem_bytes>>>(x, out);
    gate_kernel<<<128, 128>>>(sws, sbs, swe, sbe);
    final_kernel<<<51200, 256>>>(out);
}

// round 6
// speedup vs baseline: 1.4083x; 1.4083x over previous
#include <cuda_runtime.h>
#include <cuda_bf16.h>
#include <math.h>
#include <stdint.h>

// ---------------------------------------------------------------------------
// unit_gcn: stage-1 GEMM on warp-level HMMA (mma.sync m16n8k16 bf16, 3-term
// split via K-concat), stage-2 + epilogue scalar f32x2.
// Per block (n, 8 frames): P[192,200] = A'[192,192] x B'[200,192]^T
// then Y[o,tw] = sum_{s,v} P[s*64+o][t*25+v] * Af[s][v][w] + BN + res + ReLU.
// ---------------------------------------------------------------------------

typedef unsigned long long ull;

__device__ __forceinline__ ull pk2(float lo, float hi) {
    ull r; asm("mov.b64 %0, {%1, %2};" : "=l"(r) : "f"(lo), "f"(hi)); return r;
}
__device__ __forceinline__ void fma2(ull &d, ull a, ull b) {
    asm("fma.rn.f32x2 %0, %1, %2, %0;" : "+l"(d) : "l"(a), "l"(b));
}
__device__ __forceinline__ float2 up2(ull v) {
    float2 r; asm("mov.b64 {%0, %1}, %2;" : "=f"(r.x), "=f"(r.y) : "l"(v)); return r;
}
__device__ __forceinline__ uint32_t smem_u32(const void* p) {
    uint32_t a;
    asm("{ .reg .u64 t; cvta.to.shared.u64 t, %1; cvt.u32.u64 %0, t; }"
        : "=r"(a) : "l"(p));
    return a;
}
__device__ __forceinline__ void ldsm_x4(uint32_t &r0, uint32_t &r1,
                                        uint32_t &r2, uint32_t &r3, uint32_t a) {
    asm volatile("ldmatrix.sync.aligned.m8n8.x4.shared.b16 {%0,%1,%2,%3}, [%4];"
                 : "=r"(r0), "=r"(r1), "=r"(r2), "=r"(r3) : "r"(a));
}
__device__ __forceinline__ void ldsm_x2(uint32_t &r0, uint32_t &r1, uint32_t a) {
    asm volatile("ldmatrix.sync.aligned.m8n8.x2.shared.b16 {%0,%1}, [%2];"
                 : "=r"(r0), "=r"(r1) : "r"(a));
}
__device__ __forceinline__ void mma_bf16(float* d, const uint32_t* a,
                                         const uint32_t* b) {
    asm volatile(
        "mma.sync.aligned.m16n8k16.row.col.f32.bf16.bf16.f32 "
        "{%0,%1,%2,%3}, {%4,%5,%6,%7}, {%8,%9}, {%0,%1,%2,%3};"
        : "+f"(d[0]), "+f"(d[1]), "+f"(d[2]), "+f"(d[3])
        : "r"(a[0]), "r"(a[1]), "r"(a[2]), "r"(a[3]), "r"(b[0]), "r"(b[1]));
}

// ------------------------- smem layout (bytes) ------------------------------
// A'[192][200 bf16 row stride] | B'[200][200 bf16] | Afd(ull x1950) | Kc | tsum
#define A_OFF      0
#define A_BYTES    76800
#define B_OFF      76800
#define B_BYTES    80000
#define AFD_OFF    156800
#define KC_OFF     172400
#define TSUM_OFF   172656
#define SMEM_BYTES 179056
#define PS_OFF     0              /* P[192][200] f32 reuses A'/B' region */

// ------------------------- device scratch (no allocs) ----------------------
__device__ __nv_bfloat16 d_Aimg[192 * 200];   // A' prebuilt, row stride 200
__device__ float d_Afp[1950];                 // Af padded stride 26
__device__ float d_Kc[64];
__device__ float d_pp[32 * 128 * 1600];
__device__ float d_g[128 * 64 * 25];

// ------------------------------- prep --------------------------------------
__global__ void prep_kernel(const float* __restrict__ A, const float* __restrict__ PA,
                            const float* __restrict__ wd, const float* __restrict__ bd,
                            const float* __restrict__ gamma, const float* __restrict__ beta,
                            const float* __restrict__ mean, const float* __restrict__ var)
{
    int tid = threadIdx.x;
    __shared__ float ssc[64];
    if (tid < 64) {
        float sc = gamma[tid] * rsqrtf(var[tid] + 1e-5f);
        ssc[tid] = sc;
        d_Kc[tid] = (bd[tid] + bd[64 + tid] + bd[128 + tid]) * sc
                    + beta[tid] - mean[tid] * sc;
    }
    __syncthreads();
    for (int idx = tid; idx < 75; idx += blockDim.x) {
        int s = idx / 25, w = idx % 25;
        float nrm = 0.f;
        for (int v = 0; v < 25; v++) {
            float pv = PA[(s * 25 + v) * 25 + w];
            nrm += pv * pv;
        }
        nrm = sqrtf(nrm) + 1e-4f;
        for (int v = 0; v < 25; v++)
            d_Afp[(s * 25 + v) * 26 + w] =
                A[(s * 25 + v) * 25 + w] + PA[(s * 25 + v) * 25 + w] / nrm;
        d_Afp[idx * 26 + 25] = 0.f;
    }
    // A' rows: (s,o); k segs [Whi | Whi | Wlo] over c
    for (int e = tid; e < 192 * 200; e += blockDim.x) {
        int row = e / 200, k = e - row * 200;
        float val = 0.f;
        if (k < 192) {
            int s = row >> 6, o = row & 63;
            int seg = k >> 6, c = k & 63;
            float w = wd[(s * 64 + o) * 64 + c] * ssc[o];
            float hi = __bfloat162float(__float2bfloat16(w));
            val = (seg < 2) ? hi : (w - hi);
        }
        d_Aimg[e] = __float2bfloat16(val);
    }
}

// ------------------------------- main ---------------------------------------
__global__ void __launch_bounds__(640, 1)
main_kernel(const float* __restrict__ x, float* __restrict__ out)
{
    extern __shared__ char smc[];
    const uint32_t smb = smem_u32(smc);
    const int tid  = threadIdx.x;
    const int wrp  = tid >> 5;
    const int lane = tid & 31;
    const int n    = blockIdx.y;
    const int t0   = blockIdx.x * 8;

    // ---- cooperative fill ----
    {
        const uint4* src = (const uint4*)d_Aimg;
        uint4* dstA = (uint4*)(smc + A_OFF);
        for (int i = tid; i < A_BYTES / 16; i += 640) dstA[i] = src[i];

        // x -> bf16 hi/lo into B'[r][k], r = tw (200), k segs [Xhi|Xlo|Xhi]
        const float* xb = x + (size_t)n * 409600 + t0 * 25;
        __nv_bfloat16* smB = (__nv_bfloat16*)(smc + B_OFF);
        for (int e = tid; e < 12800; e += 640) {
            int c = e / 200, r = e - c * 200;
            float xv = xb[c * 6400 + r];
            __nv_bfloat16 h = __float2bfloat16(xv);
            __nv_bfloat16 l = __float2bfloat16(xv - __bfloat162float(h));
            __nv_bfloat16* br = smB + r * 200;
            br[c]       = h;
            br[64 + c]  = l;
            br[128 + c] = h;
        }
        // zero B' pad cols 192..199 (never read by ldmatrix, but keep clean)
        ull* Afd = (ull*)(smc + AFD_OFF);
        for (int i = tid; i < 1950; i += 640) {
            float f = d_Afp[i];
            Afd[i] = pk2(f, f);
        }
        float* Kcs = (float*)(smc + KC_OFF);
        if (tid < 64) Kcs[tid] = d_Kc[tid];
    }
    __syncthreads();

    // ---- stage 1: HMMA  (warp (mw,nw) owns 48x40 of P[192][200]) ----
    const int mw = wrp / 5;          // 0..3
    const int nw = wrp - mw * 5;     // 0..4

    float acc[3][5][4];
    #pragma unroll
    for (int i = 0; i < 3; i++)
        #pragma unroll
        for (int j = 0; j < 5; j++)
            #pragma unroll
            for (int q = 0; q < 4; q++) acc[i][j][q] = 0.f;

    const uint32_t aLane = (((lane & 7) + ((lane >> 3) & 1) * 8) * 200
                            + ((lane >> 4) & 1) * 8) * 2;
    const uint32_t bLane = ((lane & 7) * 200 + ((lane >> 3) & 1) * 8) * 2;
    uint32_t aAddr[3], bAddr[5];
    #pragma unroll
    for (int i = 0; i < 3; i++)
        aAddr[i] = smb + A_OFF + (uint32_t)(mw * 48 + i * 16) * 400u + aLane;
    #pragma unroll
    for (int j = 0; j < 5; j++)
        bAddr[j] = smb + B_OFF + (uint32_t)(nw * 40 + j * 8) * 400u + bLane;

    #pragma unroll 2
    for (int ks = 0; ks < 12; ks++) {
        uint32_t af[3][4], bf[5][2];
        #pragma unroll
        for (int i = 0; i < 3; i++)
            ldsm_x4(af[i][0], af[i][1], af[i][2], af[i][3], aAddr[i] + ks * 32u);
        #pragma unroll
        for (int j = 0; j < 5; j++)
            ldsm_x2(bf[j][0], bf[j][1], bAddr[j] + ks * 32u);
        #pragma unroll
        for (int i = 0; i < 3; i++)
            #pragma unroll
            for (int j = 0; j < 5; j++)
                mma_bf16(acc[i][j], af[i], bf[j]);
    }

    __syncthreads();   // all ldmatrix reads done; A'/B' region now dead

    // ---- write P to smem ----
    float* Psf = (float*)(smc + PS_OFF);
    {
        const int rl = lane >> 2;
        const int cl = (lane & 3) * 2;
        #pragma unroll
        for (int i = 0; i < 3; i++) {
            int r0 = mw * 48 + i * 16 + rl;
            #pragma unroll
            for (int j = 0; j < 5; j++) {
                int c = nw * 40 + j * 8 + cl;
                *(float2*)&Psf[r0 * 200 + c]       = make_float2(acc[i][j][0], acc[i][j][1]);
                *(float2*)&Psf[(r0 + 8) * 200 + c] = make_float2(acc[i][j][2], acc[i][j][3]);
            }
        }
    }
    float* ps = (float*)(smc + TSUM_OFF);
    for (int i = tid; i < 1600; i += 640) ps[i] = 0.f;
    __syncthreads();

    // ---- stage 2 (scalar): Y[o,tw] = sum_{s,v} P[s*64+o][t*25+v]*Af[s][v][w]
    const int m     = tid / 40;          // 4 o per thread: o = 4m..4m+3
    const int nn    = tid - m * 40;
    const int t_idx = nn / 5;
    const int w0    = (nn - t_idx * 5) * 5;
    const ull* Afd  = (const ull*)(smc + AFD_OFF);
    const float* Kcs = (const float*)(smc + KC_OFF);

    ull yacc[2][5];
    #pragma unroll
    for (int p = 0; p < 2; p++)
        #pragma unroll
        for (int j = 0; j < 5; j++) yacc[p][j] = 0ull;

    for (int s = 0; s < 3; s++) {
        const ull* afb = Afd + (s * 25) * 26 + w0;
        const float* pb = Psf + (s * 64 + 4 * m) * 200 + t_idx * 25;
        #pragma unroll 5
        for (int v = 0; v < 25; v++) {
            const ull* afr = afb + v * 26;
            ull a0 = afr[0], a1 = afr[1], a2 = afr[2], a3 = afr[3], a4 = afr[4];
            ull pv0 = pk2(pb[v],       pb[200 + v]);
            ull pv1 = pk2(pb[400 + v], pb[600 + v]);
            fma2(yacc[0][0], pv0, a0); fma2(yacc[0][1], pv0, a1);
            fma2(yacc[0][2], pv0, a2); fma2(yacc[0][3], pv0, a3);
            fma2(yacc[0][4], pv0, a4);
            fma2(yacc[1][0], pv1, a0); fma2(yacc[1][1], pv1, a1);
            fma2(yacc[1][2], pv1, a2); fma2(yacc[1][3], pv1, a3);
            fma2(yacc[1][4], pv1, a4);
        }
    }

    // ---- epilogue: BN-const + residual + ReLU ----
    float yv[2][5][2];
    #pragma unroll
    for (int p = 0; p < 2; p++) {
        int o0 = 4 * m + 2 * p;
        float kc0 = Kcs[o0], kc1 = Kcs[o0 + 1];
        const float* xr0 = x + ((size_t)(n * 64 + o0)) * 6400 + (t0 + t_idx) * 25 + w0;
        const float* xr1 = xr0 + 6400;
        #pragma unroll
        for (int j = 0; j < 5; j++) {
            float2 t2 = up2(yacc[p][j]);
            yv[p][j][0] = fmaxf(t2.x + kc0 + xr0[j], 0.f);
            yv[p][j][1] = fmaxf(t2.y + kc1 + xr1[j], 0.f);
        }
    }
    {
        float* ob = out + (size_t)n * 409600 + (t0 + t_idx) * 25 + w0;
        #pragma unroll
        for (int p = 0; p < 2; p++) {
            int o0 = 4 * m + 2 * p;
            #pragma unroll
            for (int j = 0; j < 5; j++) {
                ob[o0 * 6400 + j]       = yv[p][j][0];
                ob[(o0 + 1) * 6400 + j] = yv[p][j][1];
            }
        }
    }
    // deterministic phase-ordered per-block T-reduction
    __syncthreads();
    for (int tp = 0; tp < 8; tp++) {
        if (t_idx == tp) {
            #pragma unroll
            for (int p = 0; p < 2; p++) {
                int o0 = 4 * m + 2 * p;
                #pragma unroll
                for (int j = 0; j < 5; j++) {
                    ps[o0 * 25 + w0 + j]       += yv[p][j][0];
                    ps[(o0 + 1) * 25 + w0 + j] += yv[p][j][1];
                }
            }
        }
        __syncthreads();
    }
    float* pout = &d_pp[((size_t)blockIdx.x * 128 + n) * 1600];
    for (int idx = tid; idx < 1600; idx += 640) pout[idx] = ps[idx];
}

// ------------------------------- gate ---------------------------------------
__global__ void gate_kernel(const float* __restrict__ ws, const float* __restrict__ bs,
                            const float* __restrict__ we, const float* __restrict__ be)
{
    __shared__ float p[1600];
    __shared__ float sbuf[100];
    const int n = blockIdx.x, tid = threadIdx.x;   // 128 threads
    for (int idx = tid; idx < 1600; idx += 128) {
        float acc = 0.f;
        for (int tile = 0; tile < 32; tile++)
            acc += d_pp[((size_t)tile * 128 + n) * 1600 + idx];
        p[idx] = acc * (1.0f / 256.0f);
    }
    __syncthreads();
    if (tid < 100) {
        int r = tid / 25, v = tid % 25;
        float acc = bs[r];
        int k0 = 12 - v; if (k0 < 0) k0 = 0;
        int k1 = 36 - v; if (k1 > 24) k1 = 24;
        for (int c = 0; c < 64; c++) {
            const float* wr = &ws[(r * 64 + c) * 25];
            const float* pc = &p[c * 25 + v - 12];
            for (int k = k0; k <= k1; k++)
                acc = fmaf(pc[k], wr[k], acc);
        }
        sbuf[tid] = fmaxf(acc, 0.f);
    }
    __syncthreads();
    for (int idx = tid; idx < 1600; idx += 128) {
        int o = idx / 25, v = idx % 25;
        float z = be[o];
        #pragma unroll
        for (int r = 0; r < 4; r++)
            z = fmaf(sbuf[r * 25 + v], we[o * 4 + r], z);
        d_g[n * 1600 + idx] = 1.f + 1.f / (1.f + expf(-z));
    }
}

// ------------------------------- final --------------------------------------
__global__ void final_kernel(float* __restrict__ out)
{
    unsigned i = blockIdx.x * blockDim.x + threadIdx.x;
    float4 v = reinterpret_cast<float4*>(out)[i];
    unsigned flat = i * 4u;
    unsigned q  = flat / 25u;
    unsigned v0 = flat - q * 25u;
    unsigned co = q / 256u;
    const float* gr = d_g + (size_t)co * 25u;
    unsigned v1 = v0 + 1u; if (v1 >= 25u) v1 -= 25u;
    unsigned v2 = v0 + 2u; if (v2 >= 25u) v2 -= 25u;
    unsigned v3 = v0 + 3u; if (v3 >= 25u) v3 -= 25u;
    v.x *= gr[v0]; v.y *= gr[v1]; v.z *= gr[v2]; v.w *= gr[v3];
    reinterpret_cast<float4*>(out)[i] = v;
}

// ------------------------------ launcher -------------------------------------
extern "C" void kernel_launch(void* const* d_in, const int* in_sizes, int n_in,
                              void* d_out, int out_size)
{
    const float* x     = (const float*)d_in[0];
    const float* A     = (const float*)d_in[1];
    const float* PA    = (const float*)d_in[2];
    const float* wd    = (const float*)d_in[3];
    const float* bd    = (const float*)d_in[4];
    const float* gamma = (const float*)d_in[5];
    const float* beta  = (const float*)d_in[6];
    const float* mean  = (const float*)d_in[7];
    const float* var   = (const float*)d_in[8];
    const float* sws   = (const float*)d_in[9];
    const float* sbs   = (const float*)d_in[10];
    const float* swe   = (const float*)d_in[11];
    const float* sbe   = (const float*)d_in[12];
    float* out = (float*)d_out;

    cudaFuncSetAttribute(main_kernel, cudaFuncAttributeMaxDynamicSharedMemorySize,
                         SMEM_BYTES);

    prep_kernel<<<1, 256>>>(A, PA, wd, bd, gamma, beta, mean, var);
    dim3 grid(32, 128);
    main_kernel<<<grid, 640, SMEM_BYTES>>>(x, out);
    gate_kernel<<<128, 128>>>(sws, sbs, swe, sbe);
    final_kernel<<<51200, 256>>>(out);
}